// round 9
// baseline (speedup 1.0000x reference)
#include <cuda_runtime.h>
#include <cuda_bf16.h>
#include <math.h>
#include <stdint.h>

#define BB 64
#define NN 256
#define DD 64
#define TT 4096
#define T_TILE 256
#define TCH (TT / T_TILE)          // 16
#define THREADS 256
#define WARPS 8
#define NSLAB 32
#define SLABS (NN / NSLAB)         // 8
#define KREC 16                    // one record per (block, n)

#define DATA_ELTS (BB * NN * DD)   // 1048576
#define W_ELTS (TT * DD)           // 262144

// bf16 limb arrays (hi, mid), row-major d-contiguous
__device__ __align__(16) __nv_bfloat16 g_dlimb[2][DATA_ELTS];
__device__ __align__(16) __nv_bfloat16 g_wlimb[2][W_ELTS];
// per-(b, tc, n) combined softmax partials: (max, sum_e, sum_e*z, pad). 4 MB.
__device__ float4 g_scratch[(size_t)BB * KREC * NN];

// ---- smem layout ----
#define SM_W   0                       // 2 x (256 rows x 128 B) swizzled
#define SM_D   65536                   // 2 x (256 rows x 128 B) swizzled
#define SM_Z   131072                  // 32 x 260 floats
#define ZSTR   260
#define SM_TGT 164352                  // 256 f32
#define SM_REC 165376                  // 3 arrays of 32x9 f32 (stride 9)
#define RECSTR 9
#define SMEM_BYTES (SM_REC + 3 * 32 * RECSTR * 4)   // 168832

static __device__ __forceinline__ uint32_t smem_u32(const void* p) {
    uint32_t a;
    asm("{ .reg .u64 t; cvta.to.shared.u64 t, %1; cvt.u32.u64 %0, t; }"
        : "=r"(a) : "l"(p));
    return a;
}
static __device__ __forceinline__ void cp16(uint32_t dst, const void* src) {
    asm volatile("cp.async.cg.shared.global [%0], [%1], 16;" :: "r"(dst), "l"(src));
}
#define CP_COMMIT() asm volatile("cp.async.commit_group;")
#define CP_WAIT0()  asm volatile("cp.async.wait_group 0;" ::: "memory")

static __device__ __forceinline__ void ldsm4(uint32_t a, uint32_t r[4]) {
    asm volatile("ldmatrix.sync.aligned.m8n8.x4.shared.b16 {%0,%1,%2,%3}, [%4];"
                 : "=r"(r[0]), "=r"(r[1]), "=r"(r[2]), "=r"(r[3]) : "r"(a));
}
static __device__ __forceinline__ void mma16816(
    float d[4], const uint32_t a[4], uint32_t b0, uint32_t b1) {
    asm volatile(
        "mma.sync.aligned.m16n8k16.row.col.f32.bf16.bf16.f32 "
        "{%0,%1,%2,%3}, {%4,%5,%6,%7}, {%8,%9}, {%0,%1,%2,%3};"
        : "+f"(d[0]), "+f"(d[1]), "+f"(d[2]), "+f"(d[3])
        : "r"(a[0]), "r"(a[1]), "r"(a[2]), "r"(a[3]), "r"(b0), "r"(b1));
}

__device__ __forceinline__ unsigned fkey(float x) {
    unsigned u = __float_as_uint(x);
    return (u & 0x80000000u) ? ~u : (u | 0x80000000u);
}
__device__ __forceinline__ float finv(unsigned k) {
    unsigned u = (k & 0x80000000u) ? (k ^ 0x80000000u) : ~k;
    return __uint_as_float(u);
}

// issue a full 3-product, k64 GEMM for slab `S` into ACC (float[2][4][4])
#define GEMM_SLAB(ACC, S) do {                                              \
    _Pragma("unroll")                                                        \
    for (int _mt = 0; _mt < 2; _mt++)                                        \
        _Pragma("unroll")                                                    \
        for (int _q = 0; _q < 4; _q++)                                       \
            _Pragma("unroll")                                                \
            for (int _r = 0; _r < 4; _r++) ACC[_mt][_q][_r] = 0.f;           \
    const uint32_t _bS = bRow + (uint32_t)(NSLAB * (S)) * 128;               \
    _Pragma("unroll")                                                        \
    for (int _p = 0; _p < 3; _p++) {                                         \
        const uint32_t _aL = aRow + (uint32_t)PA[_p] * 32768;                \
        const uint32_t _bL = _bS  + (uint32_t)PB[_p] * 32768;                \
        _Pragma("unroll")                                                    \
        for (int _k = 0; _k < 4; _k++) {                                     \
            uint32_t _a0[4], _a1[4], _b0[4], _b1[4];                         \
            ldsm4(_aL + xA[_k],        _a0);                                 \
            ldsm4(_aL + 2048 + xA[_k], _a1);                                 \
            ldsm4(_bL + xB[_k],        _b0);                                 \
            ldsm4(_bL + 2048 + xB[_k], _b1);                                 \
            mma16816(ACC[0][0], _a0, _b0[0], _b0[1]);                        \
            mma16816(ACC[0][1], _a0, _b0[2], _b0[3]);                        \
            mma16816(ACC[0][2], _a0, _b1[0], _b1[1]);                        \
            mma16816(ACC[0][3], _a0, _b1[2], _b1[3]);                        \
            mma16816(ACC[1][0], _a1, _b0[0], _b0[1]);                        \
            mma16816(ACC[1][1], _a1, _b0[2], _b0[3]);                        \
            mma16816(ACC[1][2], _a1, _b1[0], _b1[1]);                        \
            mma16816(ACC[1][3], _a1, _b1[2], _b1[3]);                        \
        }                                                                    \
    }                                                                        \
} while (0)

// ---------------------------------------------------------------------------
// Prep: fp32 -> 2 bf16 limbs (hi/mid), 4 elements per thread.
// ---------------------------------------------------------------------------
__global__ void __launch_bounds__(256)
prep_kernel(const float* __restrict__ data, const float* __restrict__ W)
{
    size_t i = ((size_t)blockIdx.x * 256 + threadIdx.x) * 4;
    const bool isW = (i >= DATA_ELTS);
    size_t j = isW ? i - DATA_ELTS : i;
    float4 x = isW ? *(const float4*)(W + j) : *(const float4*)(data + j);

    float v[4] = {x.x, x.y, x.z, x.w};
    __nv_bfloat16 H[4], M[4];
    #pragma unroll
    for (int e = 0; e < 4; e++) {
        H[e] = __float2bfloat16(v[e]);
        M[e] = __float2bfloat16(v[e] - __bfloat162float(H[e]));
    }
    __nv_bfloat162 hx = __halves2bfloat162(H[0], H[1]);
    __nv_bfloat162 hy = __halves2bfloat162(H[2], H[3]);
    __nv_bfloat162 mx = __halves2bfloat162(M[0], M[1]);
    __nv_bfloat162 my = __halves2bfloat162(M[2], M[3]);
    if (isW) {
        ((__nv_bfloat162*)(&g_wlimb[0][j]))[0] = hx;
        ((__nv_bfloat162*)(&g_wlimb[0][j]))[1] = hy;
        ((__nv_bfloat162*)(&g_wlimb[1][j]))[0] = mx;
        ((__nv_bfloat162*)(&g_wlimb[1][j]))[1] = my;
    } else {
        ((__nv_bfloat162*)(&g_dlimb[0][j]))[0] = hx;
        ((__nv_bfloat162*)(&g_dlimb[0][j]))[1] = hy;
        ((__nv_bfloat162*)(&g_dlimb[1][j]))[0] = mx;
        ((__nv_bfloat162*)(&g_dlimb[1][j]))[1] = my;
    }
}

// ---------------------------------------------------------------------------
// Main: software-pipelined mma.sync GEMM + scan + block-combined partials.
// grid (TCH, BB), 256 threads, 1 CTA/SM.
// ---------------------------------------------------------------------------
extern "C" __global__ void __launch_bounds__(THREADS, 1)
main_kernel(const float* __restrict__ targets)
{
    extern __shared__ __align__(1024) char smem[];
    const uint32_t sb = smem_u32(smem);
    const int tc   = blockIdx.x;
    const int b    = blockIdx.y;
    const int tid  = threadIdx.x;
    const int w    = tid >> 5;
    const int lane = tid & 31;

    // ---- prologue: stage W limbs, data limbs (swizzled rows), targets ----
    #pragma unroll
    for (int kq = 0; kq < 16; kq++) {
        int i = kq * THREADS + tid;
        int limb = i >> 11, rem = i & 2047, row = rem >> 3, c = rem & 7;
        cp16(sb + SM_W + limb * 32768 + row * 128 + ((c ^ (row & 7)) << 4),
             &g_wlimb[limb][(size_t)(tc * T_TILE + row) * DD + c * 8]);
    }
    #pragma unroll
    for (int kq = 0; kq < 16; kq++) {
        int i = kq * THREADS + tid;
        int limb = i >> 11, rem = i & 2047, row = rem >> 3, c = rem & 7;
        cp16(sb + SM_D + limb * 32768 + row * 128 + ((c ^ (row & 7)) << 4),
             &g_dlimb[limb][((size_t)b * NN + row) * DD + c * 8]);
    }
    if (tid < 64) cp16(sb + SM_TGT + tid * 16, targets + (size_t)b * NN + tid * 4);
    CP_COMMIT();
    CP_WAIT0();
    __syncthreads();

    // fragment lane decomposition
    const int l7 = lane & 7;
    const int t1 = (lane >> 3) & 1;
    const int t2 = lane >> 4;

    uint32_t xA[4], xB[4];
    #pragma unroll
    for (int k = 0; k < 4; k++) {
        xA[k] = (uint32_t)(((2 * k + t2) ^ l7) << 4);
        xB[k] = (uint32_t)(((2 * k + t1) ^ l7) << 4);
    }
    const uint32_t aRow = sb + SM_W + (uint32_t)(32 * w + 8 * t1 + l7) * 128;
    const uint32_t bRow = sb + SM_D + (uint32_t)(8 * t2 + l7) * 128;

    const int PA[3] = {0, 0, 1};   // (hh)(hm)(mh)
    const int PB[3] = {0, 1, 0};

    float* zw = (float*)(smem + SM_Z);
    const float* s_tgt = (const float*)(smem + SM_TGT);
    float* recM = (float*)(smem + SM_REC);
    float* recS = recM + 32 * RECSTR;
    float* recP = recS + 32 * RECSTR;

    float cum = 0.f;
    float4* srec = &g_scratch[((size_t)b * KREC + tc) * NN];

    // transpose-store constants
    const int r0 = lane >> 2;
    const int c0 = 2 * (lane & 3);

    float acc[2][2][4][4];
    GEMM_SLAB(acc[0], 0);          // prime the pipeline

    for (int s = 0; s < SLABS; s++) {
        const int cur = s & 1;

        // ---- transpose-store z[n_local][t_local] from acc[cur] ----
        #pragma unroll
        for (int mt = 0; mt < 2; mt++) {
            const int tg = 32 * w + 16 * mt + r0;
            #pragma unroll
            for (int q = 0; q < 4; q++) {
                const int nl = 8 * q + c0;
                zw[nl * ZSTR + tg]           = acc[cur][mt][q][0];
                zw[(nl + 1) * ZSTR + tg]     = acc[cur][mt][q][1];
                zw[nl * ZSTR + tg + 8]       = acc[cur][mt][q][2];
                zw[(nl + 1) * ZSTR + tg + 8] = acc[cur][mt][q][3];
            }
        }
        __syncwarp();

        // ---- issue next slab's GEMM (tensor pipe busy under epilogue) ----
        if (s + 1 < SLABS) GEMM_SLAB(acc[cur ^ 1], s + 1);

        // ---- epilogue: cum loglik scan + REDUX softmax partials ----
        float mO = 0.f, sO = 0.f, pO = 0.f;
        #pragma unroll
        for (int j = 0; j < NSLAB; j++) {
            float z  = zw[j * ZSTR + tid];
            float tn = s_tgt[s * NSLAB + j];
            float cv = cum;
            float r  = tn - z;
            cum = fmaf(-0.5f * r, r, cum);

            unsigned km = __reduce_max_sync(0xffffffffu, fkey(cv));
            float m = finv(km);
            float e = __expf(cv - m);
            int ie = __float2int_rn(e * 16777216.0f);           // 2^24
            int ip = __float2int_rn(e * z * 131072.0f);         // 2^17
            int se = __reduce_add_sync(0xffffffffu, ie);
            int sp = __reduce_add_sync(0xffffffffu, ip);
            if (lane == j) {
                mO = m;
                sO = (float)se * 5.9604644775390625e-8f;        // 2^-24
                pO = (float)sp * 7.62939453125e-6f;             // 2^-17
            }
        }
        // lane j holds record for n = s*32 + j; stash to smem
        recM[lane * RECSTR + w] = mO;
        recS[lane * RECSTR + w] = sO;
        recP[lane * RECSTR + w] = pO;
        __syncthreads();

        // ---- cross-warp LSE combine: 8 records -> 1 per n ----
        {
            const int n  = tid >> 3;       // 0..31
            const int wr = tid & 7;
            float m = recM[n * RECSTR + wr];
            float S = recS[n * RECSTR + wr];
            float P = recP[n * RECSTR + wr];
            #pragma unroll
            for (int o = 1; o < 8; o <<= 1) {
                float om = __shfl_xor_sync(0xffffffffu, m, o);
                float os = __shfl_xor_sync(0xffffffffu, S, o);
                float op = __shfl_xor_sync(0xffffffffu, P, o);
                float mx = fmaxf(m, om);
                float ea = __expf(m - mx);
                float eb = __expf(om - mx);
                S = fmaf(S, ea, os * eb);
                P = fmaf(P, ea, op * eb);
                m = mx;
            }
            if (wr == 0)
                srec[s * NSLAB + n] = make_float4(m, S, P, 0.f);
        }
        __syncthreads();
    }
}

// ---------------------------------------------------------------------------
// Merge: 4 threads per (b,n), 4 records each; two-pass stable softmax.
// n==0 falls out naturally (all maxes 0 -> uniform -> pred0).
// ---------------------------------------------------------------------------
extern "C" __global__ void __launch_bounds__(256)
merge_kernel(float* __restrict__ out)
{
    const int gp = blockIdx.x * 64 + (threadIdx.x >> 2);
    const int q  = threadIdx.x & 3;
    const int b  = gp >> 8;
    const int n  = gp & 255;
    const float4* base = &g_scratch[(size_t)b * KREC * NN + n];

    float M = -3.4e38f;
    #pragma unroll
    for (int i = 0; i < 4; i++)
        M = fmaxf(M, __ldg(&base[(size_t)(q + 4 * i) * NN]).x);

    float gM = M;
    gM = fmaxf(gM, __shfl_xor_sync(0xffffffffu, gM, 1));
    gM = fmaxf(gM, __shfl_xor_sync(0xffffffffu, gM, 2));

    float S = 0.f, P = 0.f;
    #pragma unroll
    for (int i = 0; i < 4; i++) {
        float4 v = __ldg(&base[(size_t)(q + 4 * i) * NN]);
        float e = __expf(v.x - gM);
        S = fmaf(v.y, e, S);
        P = fmaf(v.z, e, P);
    }
    S += __shfl_xor_sync(0xffffffffu, S, 1);
    P += __shfl_xor_sync(0xffffffffu, P, 1);
    S += __shfl_xor_sync(0xffffffffu, S, 2);
    P += __shfl_xor_sync(0xffffffffu, P, 2);

    if (q == 0)
        out[(size_t)b * NN + n] = P / S;
}

// ---------------------------------------------------------------------------
extern "C" void kernel_launch(void* const* d_in, const int* in_sizes, int n_in,
                              void* d_out, int out_size)
{
    const float* data    = (const float*)d_in[0];   // (64, 256, 64)
    const float* targets = (const float*)d_in[1];   // (64, 256)
    const float* W       = (const float*)d_in[2];   // (4096, 64, 1)
    float* out = (float*)d_out;                     // (64, 256)

    cudaFuncSetAttribute(main_kernel,
                         cudaFuncAttributeMaxDynamicSharedMemorySize,
                         SMEM_BYTES);

    prep_kernel<<<(DATA_ELTS + W_ELTS) / 1024, 256>>>(data, W);
    main_kernel<<<dim3(TCH, BB), THREADS, SMEM_BYTES>>>(targets);
    merge_kernel<<<256, 256>>>(out);
}

// round 10
// speedup vs baseline: 1.4222x; 1.4222x over previous
#include <cuda_runtime.h>
#include <cuda_bf16.h>
#include <math.h>
#include <stdint.h>

#define BB 64
#define NN 256
#define DD 64
#define TT 4096
#define T_TILE 256
#define TCH (TT / T_TILE)          // 16
#define THREADS 256
#define WARPS 8
#define NSLAB 32
#define SLABS (NN / NSLAB)         // 8
#define KREC 128                   // records per (b,n): 16 tc x 8 warps

#define DATA_ELTS (BB * NN * DD)   // 1048576
#define W_ELTS (TT * DD)           // 262144

// bf16 limb arrays (hi, mid), row-major d-contiguous
__device__ __align__(16) __nv_bfloat16 g_dlimb[2][DATA_ELTS];
__device__ __align__(16) __nv_bfloat16 g_wlimb[2][W_ELTS];
// per-(b, n, k) LSE records: (lse, r). 16 MB, k-contiguous for merge.
__device__ float2 g_rec[(size_t)BB * NN * KREC];

// ---- smem layout ----
#define SM_W   0                       // 2 x (256 rows x 128 B) swizzled
#define SM_D   65536                   // 2 x (256 rows x 128 B) swizzled
#define SM_Z   131072                  // 32 x 260 floats
#define ZSTR   260
#define SM_CV  164352                  // 32 x 260 floats
#define SM_TGT 197632                  // 256 f32
#define SMEM_BYTES 198656

static __device__ __forceinline__ uint32_t smem_u32(const void* p) {
    uint32_t a;
    asm("{ .reg .u64 t; cvta.to.shared.u64 t, %1; cvt.u32.u64 %0, t; }"
        : "=r"(a) : "l"(p));
    return a;
}
static __device__ __forceinline__ void cp16(uint32_t dst, const void* src) {
    asm volatile("cp.async.cg.shared.global [%0], [%1], 16;" :: "r"(dst), "l"(src));
}
#define CP_COMMIT() asm volatile("cp.async.commit_group;")
#define CP_WAIT0()  asm volatile("cp.async.wait_group 0;" ::: "memory")

static __device__ __forceinline__ void ldsm4(uint32_t a, uint32_t r[4]) {
    asm volatile("ldmatrix.sync.aligned.m8n8.x4.shared.b16 {%0,%1,%2,%3}, [%4];"
                 : "=r"(r[0]), "=r"(r[1]), "=r"(r[2]), "=r"(r[3]) : "r"(a));
}
static __device__ __forceinline__ void mma16816(
    float d[4], const uint32_t a[4], uint32_t b0, uint32_t b1) {
    asm volatile(
        "mma.sync.aligned.m16n8k16.row.col.f32.bf16.bf16.f32 "
        "{%0,%1,%2,%3}, {%4,%5,%6,%7}, {%8,%9}, {%0,%1,%2,%3};"
        : "+f"(d[0]), "+f"(d[1]), "+f"(d[2]), "+f"(d[3])
        : "r"(a[0]), "r"(a[1]), "r"(a[2]), "r"(a[3]), "r"(b0), "r"(b1));
}

// ---------------------------------------------------------------------------
// Prep: fp32 -> 2 bf16 limbs (hi/mid), 4 elements per thread.
// ---------------------------------------------------------------------------
__global__ void __launch_bounds__(256)
prep_kernel(const float* __restrict__ data, const float* __restrict__ W)
{
    size_t i = ((size_t)blockIdx.x * 256 + threadIdx.x) * 4;
    const bool isW = (i >= DATA_ELTS);
    size_t j = isW ? i - DATA_ELTS : i;
    float4 x = isW ? *(const float4*)(W + j) : *(const float4*)(data + j);

    float v[4] = {x.x, x.y, x.z, x.w};
    __nv_bfloat16 H[4], M[4];
    #pragma unroll
    for (int e = 0; e < 4; e++) {
        H[e] = __float2bfloat16(v[e]);
        M[e] = __float2bfloat16(v[e] - __bfloat162float(H[e]));
    }
    __nv_bfloat162 hx = __halves2bfloat162(H[0], H[1]);
    __nv_bfloat162 hy = __halves2bfloat162(H[2], H[3]);
    __nv_bfloat162 mx = __halves2bfloat162(M[0], M[1]);
    __nv_bfloat162 my = __halves2bfloat162(M[2], M[3]);
    if (isW) {
        ((__nv_bfloat162*)(&g_wlimb[0][j]))[0] = hx;
        ((__nv_bfloat162*)(&g_wlimb[0][j]))[1] = hy;
        ((__nv_bfloat162*)(&g_wlimb[1][j]))[0] = mx;
        ((__nv_bfloat162*)(&g_wlimb[1][j]))[1] = my;
    } else {
        ((__nv_bfloat162*)(&g_dlimb[0][j]))[0] = hx;
        ((__nv_bfloat162*)(&g_dlimb[0][j]))[1] = hy;
        ((__nv_bfloat162*)(&g_dlimb[1][j]))[0] = mx;
        ((__nv_bfloat162*)(&g_dlimb[1][j]))[1] = my;
    }
}

// ---------------------------------------------------------------------------
// Main: mma.sync 2-limb GEMM (R7 structure) + lane-transposed epilogue.
// grid (TCH, BB), 256 threads, 1 CTA/SM. Warps fully independent in loop.
// ---------------------------------------------------------------------------
extern "C" __global__ void __launch_bounds__(THREADS, 1)
main_kernel(const float* __restrict__ targets)
{
    extern __shared__ __align__(1024) char smem[];
    const uint32_t sb = smem_u32(smem);
    const int tc   = blockIdx.x;
    const int b    = blockIdx.y;
    const int tid  = threadIdx.x;
    const int w    = tid >> 5;
    const int lane = tid & 31;

    // ---- prologue: stage W limbs, data limbs (swizzled rows), targets ----
    #pragma unroll
    for (int kq = 0; kq < 16; kq++) {
        int i = kq * THREADS + tid;
        int limb = i >> 11, rem = i & 2047, row = rem >> 3, c = rem & 7;
        cp16(sb + SM_W + limb * 32768 + row * 128 + ((c ^ (row & 7)) << 4),
             &g_wlimb[limb][(size_t)(tc * T_TILE + row) * DD + c * 8]);
    }
    #pragma unroll
    for (int kq = 0; kq < 16; kq++) {
        int i = kq * THREADS + tid;
        int limb = i >> 11, rem = i & 2047, row = rem >> 3, c = rem & 7;
        cp16(sb + SM_D + limb * 32768 + row * 128 + ((c ^ (row & 7)) << 4),
             &g_dlimb[limb][((size_t)b * NN + row) * DD + c * 8]);
    }
    if (tid < 64) cp16(sb + SM_TGT + tid * 16, targets + (size_t)b * NN + tid * 4);
    CP_COMMIT();
    CP_WAIT0();
    __syncthreads();

    // fragment lane decomposition
    const int l7 = lane & 7;
    const int t1 = (lane >> 3) & 1;
    const int t2 = lane >> 4;

    uint32_t xA[4], xB[4];
    #pragma unroll
    for (int k = 0; k < 4; k++) {
        xA[k] = (uint32_t)(((2 * k + t2) ^ l7) << 4);
        xB[k] = (uint32_t)(((2 * k + t1) ^ l7) << 4);
    }
    const uint32_t aRow = sb + SM_W + (uint32_t)(32 * w + 8 * t1 + l7) * 128;
    const uint32_t bRow = sb + SM_D + (uint32_t)(8 * t2 + l7) * 128;

    const int PA[3] = {0, 0, 1};   // (hh)(hm)(mh)
    const int PB[3] = {0, 1, 0};

    float* zw  = (float*)(smem + SM_Z);
    float* cvw = (float*)(smem + SM_CV);
    const float* s_tgt = (const float*)(smem + SM_TGT);

    float cum = 0.f;
    const int gw = tc * WARPS + w;

    const int r0 = lane >> 2;
    const int c0 = 2 * (lane & 3);

    for (int s = 0; s < SLABS; s++) {
        // ---- GEMM: 32 tasks x 32 n x k64, 3 limb products ----
        float acc[2][4][4];
        #pragma unroll
        for (int mt = 0; mt < 2; mt++)
            #pragma unroll
            for (int q = 0; q < 4; q++)
                #pragma unroll
                for (int r = 0; r < 4; r++) acc[mt][q][r] = 0.f;

        const uint32_t bSlab = bRow + (uint32_t)(NSLAB * s) * 128;
        #pragma unroll
        for (int p = 0; p < 3; p++) {
            const uint32_t aL = aRow + (uint32_t)PA[p] * 32768;
            const uint32_t bL = bSlab + (uint32_t)PB[p] * 32768;
            #pragma unroll
            for (int k = 0; k < 4; k++) {
                uint32_t a0[4], a1[4], b0[4], b1[4];
                ldsm4(aL + xA[k],        a0);
                ldsm4(aL + 2048 + xA[k], a1);
                ldsm4(bL + xB[k],        b0);
                ldsm4(bL + 2048 + xB[k], b1);
                mma16816(acc[0][0], a0, b0[0], b0[1]);
                mma16816(acc[0][1], a0, b0[2], b0[3]);
                mma16816(acc[0][2], a0, b1[0], b1[1]);
                mma16816(acc[0][3], a0, b1[2], b1[3]);
                mma16816(acc[1][0], a1, b0[0], b0[1]);
                mma16816(acc[1][1], a1, b0[2], b0[3]);
                mma16816(acc[1][2], a1, b1[0], b1[1]);
                mma16816(acc[1][3], a1, b1[2], b1[3]);
            }
        }

        // ---- transpose-store z[n_local][t_local] ----
        #pragma unroll
        for (int mt = 0; mt < 2; mt++) {
            const int tg = 32 * w + 16 * mt + r0;
            #pragma unroll
            for (int q = 0; q < 4; q++) {
                const int nl = 8 * q + c0;
                zw[nl * ZSTR + tg]           = acc[mt][q][0];
                zw[(nl + 1) * ZSTR + tg]     = acc[mt][q][1];
                zw[nl * ZSTR + tg + 8]       = acc[mt][q][2];
                zw[(nl + 1) * ZSTR + tg + 8] = acc[mt][q][3];
            }
        }
        __syncwarp();

        // ---- phase A: cumulative loglik scan (thread = task) ----
        #pragma unroll
        for (int j = 0; j < NSLAB; j++) {
            float z  = zw[j * ZSTR + tid];
            float tn = s_tgt[s * NSLAB + j];
            cvw[j * ZSTR + tid] = cum;       // alphas for step s*32+j
            float r = tn - z;
            cum = fmaf(-0.5f * r, r, cum);
        }
        __syncwarp();

        // ---- phase B: per-n in-lane reduction over warp's 32 tasks ----
        {
            const float* cvr = cvw + lane * ZSTR + 32 * w;
            const float* zr  = zw  + lane * ZSTR + 32 * w;

            float cv[32];
            #pragma unroll
            for (int k = 0; k < 8; k++) {
                float4 v = *(const float4*)(cvr + 4 * k);
                cv[4*k] = v.x; cv[4*k+1] = v.y; cv[4*k+2] = v.z; cv[4*k+3] = v.w;
            }
            float tm[16];
            #pragma unroll
            for (int k = 0; k < 16; k++) tm[k] = fmaxf(cv[k], cv[k + 16]);
            #pragma unroll
            for (int h = 8; h >= 1; h >>= 1)
                #pragma unroll
                for (int k = 0; k < h; k++) tm[k] = fmaxf(tm[k], tm[k + h]);
            const float m = tm[0];

            float S = 0.f, P = 0.f;
            #pragma unroll
            for (int k = 0; k < 8; k++) {
                float4 zv = *(const float4*)(zr + 4 * k);
                float e0 = __expf(cv[4*k]   - m);
                float e1 = __expf(cv[4*k+1] - m);
                float e2 = __expf(cv[4*k+2] - m);
                float e3 = __expf(cv[4*k+3] - m);
                S += (e0 + e1) + (e2 + e3);
                P = fmaf(e0, zv.x, P);
                P = fmaf(e1, zv.y, P);
                P = fmaf(e2, zv.z, P);
                P = fmaf(e3, zv.w, P);
            }
            const int n = s * NSLAB + lane;
            g_rec[((size_t)b * NN + n) * KREC + gw] =
                make_float2(m + __logf(S), __fdividef(P, S));
        }
        __syncwarp();   // zw/cvw reads done before next slab overwrites
    }
}

// ---------------------------------------------------------------------------
// Merge: 8 threads per (b,n), 16 LSE records each, coalesced k-major reads.
// n==0 falls out naturally (all partials uniform -> pred0).
// ---------------------------------------------------------------------------
extern "C" __global__ void __launch_bounds__(256)
merge_kernel(float* __restrict__ out)
{
    const int gp = blockIdx.x * 32 + (threadIdx.x >> 3);
    const int q  = threadIdx.x & 7;
    const int b  = gp >> 8;
    const int n  = gp & 255;
    const float2* base = &g_rec[((size_t)b * NN + n) * KREC];

    float2 rec[16];
    float M = -3.4e38f;
    #pragma unroll
    for (int i = 0; i < 16; i++) {
        rec[i] = __ldg(&base[i * 8 + q]);
        M = fmaxf(M, rec[i].x);
    }
    float gM = M;
    gM = fmaxf(gM, __shfl_xor_sync(0xffffffffu, gM, 1));
    gM = fmaxf(gM, __shfl_xor_sync(0xffffffffu, gM, 2));
    gM = fmaxf(gM, __shfl_xor_sync(0xffffffffu, gM, 4));

    float S = 0.f, P = 0.f;
    #pragma unroll
    for (int i = 0; i < 16; i++) {
        float e = __expf(rec[i].x - gM);
        S += e;
        P = fmaf(rec[i].y, e, P);
    }
    S += __shfl_xor_sync(0xffffffffu, S, 1);
    P += __shfl_xor_sync(0xffffffffu, P, 1);
    S += __shfl_xor_sync(0xffffffffu, S, 2);
    P += __shfl_xor_sync(0xffffffffu, P, 2);
    S += __shfl_xor_sync(0xffffffffu, S, 4);
    P += __shfl_xor_sync(0xffffffffu, P, 4);

    if (q == 0)
        out[(size_t)b * NN + n] = P / S;
}

// ---------------------------------------------------------------------------
extern "C" void kernel_launch(void* const* d_in, const int* in_sizes, int n_in,
                              void* d_out, int out_size)
{
    const float* data    = (const float*)d_in[0];   // (64, 256, 64)
    const float* targets = (const float*)d_in[1];   // (64, 256)
    const float* W       = (const float*)d_in[2];   // (4096, 64, 1)
    float* out = (float*)d_out;                     // (64, 256)

    cudaFuncSetAttribute(main_kernel,
                         cudaFuncAttributeMaxDynamicSharedMemorySize,
                         SMEM_BYTES);

    prep_kernel<<<(DATA_ELTS + W_ELTS) / 1024, 256>>>(data, W);
    main_kernel<<<dim3(TCH, BB), THREADS, SMEM_BYTES>>>(targets);
    merge_kernel<<<512, 256>>>(out);
}

// round 11
// speedup vs baseline: 1.4767x; 1.0383x over previous
#include <cuda_runtime.h>
#include <cuda_bf16.h>
#include <math.h>
#include <stdint.h>

#define BB 64
#define NN 256
#define DD 64
#define TT 4096
#define T_TILE 128
#define TCH (TT / T_TILE)          // 32
#define THREADS 128
#define WARPS 4
#define NSLAB 32
#define SLABS (NN / NSLAB)         // 8
#define KREC 128                   // records per (b,n): 32 tc x 4 warps

#define DATA_ELTS (BB * NN * DD)   // 1048576
#define W_ELTS (TT * DD)           // 262144

// bf16 limb arrays (hi, mid), row-major d-contiguous
__device__ __align__(16) __nv_bfloat16 g_dlimb[2][DATA_ELTS];
__device__ __align__(16) __nv_bfloat16 g_wlimb[2][W_ELTS];
// per-(b, n, k) LSE records: (lse, r). 16 MB, k-contiguous for merge.
__device__ float2 g_rec[(size_t)BB * NN * KREC];

// ---- smem layout (per CTA, 84 KB -> 2 CTAs/SM) ----
#define SM_W   0                       // 2 limbs x (128 rows x 128 B)
#define SM_D   32768                   // 2 buffers x 2 limbs x (32 x 128 B)
#define SM_Z   49152                   // 32 x 132 floats
#define ZSTR   132
#define SM_CV  66048                   // 32 x 132 floats
#define SM_TGT 82944                   // 256 f32
#define SMEM_BYTES 83968

static __device__ __forceinline__ uint32_t smem_u32(const void* p) {
    uint32_t a;
    asm("{ .reg .u64 t; cvta.to.shared.u64 t, %1; cvt.u32.u64 %0, t; }"
        : "=r"(a) : "l"(p));
    return a;
}
static __device__ __forceinline__ void cp16(uint32_t dst, const void* src) {
    asm volatile("cp.async.cg.shared.global [%0], [%1], 16;" :: "r"(dst), "l"(src));
}
#define CP_COMMIT() asm volatile("cp.async.commit_group;")
#define CP_WAIT1()  asm volatile("cp.async.wait_group 1;" ::: "memory")

static __device__ __forceinline__ void ldsm4(uint32_t a, uint32_t r[4]) {
    asm volatile("ldmatrix.sync.aligned.m8n8.x4.shared.b16 {%0,%1,%2,%3}, [%4];"
                 : "=r"(r[0]), "=r"(r[1]), "=r"(r[2]), "=r"(r[3]) : "r"(a));
}
static __device__ __forceinline__ void mma16816(
    float d[4], const uint32_t a[4], uint32_t b0, uint32_t b1) {
    asm volatile(
        "mma.sync.aligned.m16n8k16.row.col.f32.bf16.bf16.f32 "
        "{%0,%1,%2,%3}, {%4,%5,%6,%7}, {%8,%9}, {%0,%1,%2,%3};"
        : "+f"(d[0]), "+f"(d[1]), "+f"(d[2]), "+f"(d[3])
        : "r"(a[0]), "r"(a[1]), "r"(a[2]), "r"(a[3]), "r"(b0), "r"(b1));
}

// ---------------------------------------------------------------------------
// Prep: fp32 -> 2 bf16 limbs (hi/mid), 8 elements per thread (MLP=2).
// ---------------------------------------------------------------------------
__global__ void __launch_bounds__(256)
prep_kernel(const float* __restrict__ data, const float* __restrict__ W)
{
    size_t i = ((size_t)blockIdx.x * 256 + threadIdx.x) * 8;
    const bool isW = (i >= DATA_ELTS);
    size_t j = isW ? i - DATA_ELTS : i;
    const float* src = isW ? (W + j) : (data + j);
    float4 x0 = *(const float4*)src;
    float4 x1 = *(const float4*)(src + 4);

    float v[8] = {x0.x, x0.y, x0.z, x0.w, x1.x, x1.y, x1.z, x1.w};
    uint32_t hp[4], mp[4];
    #pragma unroll
    for (int e = 0; e < 4; e++) {
        __nv_bfloat16 h0 = __float2bfloat16(v[2*e]);
        __nv_bfloat16 h1 = __float2bfloat16(v[2*e+1]);
        __nv_bfloat16 m0 = __float2bfloat16(v[2*e]   - __bfloat162float(h0));
        __nv_bfloat16 m1 = __float2bfloat16(v[2*e+1] - __bfloat162float(h1));
        __nv_bfloat162 hh = __halves2bfloat162(h0, h1);
        __nv_bfloat162 mm = __halves2bfloat162(m0, m1);
        hp[e] = *(uint32_t*)&hh;
        mp[e] = *(uint32_t*)&mm;
    }
    uint4 hv = make_uint4(hp[0], hp[1], hp[2], hp[3]);
    uint4 mv = make_uint4(mp[0], mp[1], mp[2], mp[3]);
    if (isW) {
        *(uint4*)(&g_wlimb[0][j]) = hv;
        *(uint4*)(&g_wlimb[1][j]) = mv;
    } else {
        *(uint4*)(&g_dlimb[0][j]) = hv;
        *(uint4*)(&g_dlimb[1][j]) = mv;
    }
}

// ---------------------------------------------------------------------------
// Main: 2 CTAs/SM, per-slab double-buffered data staging, mma.sync GEMM,
// lane-transposed epilogue. grid (TCH, BB), 128 threads.
// ---------------------------------------------------------------------------
extern "C" __global__ void __launch_bounds__(THREADS, 2)
main_kernel(const float* __restrict__ targets)
{
    extern __shared__ __align__(1024) char smem[];
    const uint32_t sb = smem_u32(smem);
    const int tc   = blockIdx.x;
    const int b    = blockIdx.y;
    const int tid  = threadIdx.x;
    const int w    = tid >> 5;
    const int lane = tid & 31;

    const __nv_bfloat16* dbase0 = &g_dlimb[0][(size_t)b * NN * DD];
    const __nv_bfloat16* dbase1 = &g_dlimb[1][(size_t)b * NN * DD];

    // ---- prologue group 0: W tile (2 limbs x 128 rows), targets, slab 0 ----
    #pragma unroll
    for (int kq = 0; kq < 16; kq++) {         // 2048 chunks / 128 thr
        int i = kq * THREADS + tid;
        int limb = i >> 10, rem = i & 1023, row = rem >> 3, c = rem & 7;
        cp16(sb + SM_W + limb * 16384 + row * 128 + ((c ^ (row & 7)) << 4),
             &g_wlimb[limb][(size_t)(tc * T_TILE + row) * DD + c * 8]);
    }
    if (tid < 64) cp16(sb + SM_TGT + tid * 16, targets + (size_t)b * NN + tid * 4);
    {   // slab 0 -> buffer 0
        #pragma unroll
        for (int kq = 0; kq < 4; kq++) {
            int i = kq * THREADS + tid;       // 512 chunks
            int limb = i >> 8, rem = i & 255, row = rem >> 3, c = rem & 7;
            const __nv_bfloat16* src = limb ? dbase1 : dbase0;
            cp16(sb + SM_D + limb * 4096 + row * 128 + ((c ^ (row & 7)) << 4),
                 src + (size_t)row * DD + c * 8);
        }
    }
    CP_COMMIT();
    {   // group 1: slab 1 -> buffer 1
        #pragma unroll
        for (int kq = 0; kq < 4; kq++) {
            int i = kq * THREADS + tid;
            int limb = i >> 8, rem = i & 255, row = rem >> 3, c = rem & 7;
            const __nv_bfloat16* src = limb ? dbase1 : dbase0;
            cp16(sb + SM_D + 8192 + limb * 4096 + row * 128 + ((c ^ (row & 7)) << 4),
                 src + (size_t)(NSLAB + row) * DD + c * 8);
        }
    }
    CP_COMMIT();
    CP_WAIT1();                               // group 0 (W, tgt, slab0) done
    __syncthreads();

    // fragment lane decomposition
    const int l7 = lane & 7;
    const int t1 = (lane >> 3) & 1;
    const int t2 = lane >> 4;

    uint32_t xA[4], xB[4];
    #pragma unroll
    for (int k = 0; k < 4; k++) {
        xA[k] = (uint32_t)(((2 * k + t2) ^ l7) << 4);
        xB[k] = (uint32_t)(((2 * k + t1) ^ l7) << 4);
    }
    const uint32_t aRow  = sb + SM_W + (uint32_t)(32 * w + 8 * t1 + l7) * 128;
    const uint32_t bRow0 = sb + SM_D + (uint32_t)(8 * t2 + l7) * 128;

    const int PA[3] = {0, 0, 1};   // (hh)(hm)(mh)
    const int PB[3] = {0, 1, 0};

    float* zw  = (float*)(smem + SM_Z);
    float* cvw = (float*)(smem + SM_CV);
    const float* s_tgt = (const float*)(smem + SM_TGT);

    float cum = 0.f;
    const int gw = tc * WARPS + w;

    const int r0 = lane >> 2;
    const int c0 = 2 * (lane & 3);

    for (int s = 0; s < SLABS; s++) {
        const uint32_t bR = bRow0 + (uint32_t)((s & 1) * 8192);

        // ---- GEMM: 32 tasks x 32 n x k64, 3 limb products ----
        float acc[2][4][4];
        #pragma unroll
        for (int mt = 0; mt < 2; mt++)
            #pragma unroll
            for (int q = 0; q < 4; q++)
                #pragma unroll
                for (int r = 0; r < 4; r++) acc[mt][q][r] = 0.f;

        #pragma unroll
        for (int p = 0; p < 3; p++) {
            const uint32_t aL = aRow + (uint32_t)PA[p] * 16384;
            const uint32_t bL = bR   + (uint32_t)PB[p] * 4096;
            #pragma unroll
            for (int k = 0; k < 4; k++) {
                uint32_t a0[4], a1[4], b0[4], b1[4];
                ldsm4(aL + xA[k],        a0);
                ldsm4(aL + 2048 + xA[k], a1);
                ldsm4(bL + xB[k],        b0);
                ldsm4(bL + 2048 + xB[k], b1);
                mma16816(acc[0][0], a0, b0[0], b0[1]);
                mma16816(acc[0][1], a0, b0[2], b0[3]);
                mma16816(acc[0][2], a0, b1[0], b1[1]);
                mma16816(acc[0][3], a0, b1[2], b1[3]);
                mma16816(acc[1][0], a1, b0[0], b0[1]);
                mma16816(acc[1][1], a1, b0[2], b0[3]);
                mma16816(acc[1][2], a1, b1[0], b1[1]);
                mma16816(acc[1][3], a1, b1[2], b1[3]);
            }
        }

        // ---- transpose-store z[n_local][t_local] ----
        #pragma unroll
        for (int mt = 0; mt < 2; mt++) {
            const int tg = 32 * w + 16 * mt + r0;
            #pragma unroll
            for (int q = 0; q < 4; q++) {
                const int nl = 8 * q + c0;
                zw[nl * ZSTR + tg]           = acc[mt][q][0];
                zw[(nl + 1) * ZSTR + tg]     = acc[mt][q][1];
                zw[nl * ZSTR + tg + 8]       = acc[mt][q][2];
                zw[(nl + 1) * ZSTR + tg + 8] = acc[mt][q][3];
            }
        }
        __syncwarp();

        // ---- phase A: cumulative loglik scan (thread = task) ----
        #pragma unroll
        for (int j = 0; j < NSLAB; j++) {
            float z  = zw[j * ZSTR + tid];
            float tn = s_tgt[s * NSLAB + j];
            cvw[j * ZSTR + tid] = cum;
            float r = tn - z;
            cum = fmaf(-0.5f * r, r, cum);
        }
        __syncwarp();

        // ---- phase B: per-n in-lane reduction over warp's 32 tasks ----
        {
            const float* cvr = cvw + lane * ZSTR + 32 * w;
            const float* zr  = zw  + lane * ZSTR + 32 * w;

            float cv[32];
            #pragma unroll
            for (int k = 0; k < 8; k++) {
                float4 v = *(const float4*)(cvr + 4 * k);
                cv[4*k] = v.x; cv[4*k+1] = v.y; cv[4*k+2] = v.z; cv[4*k+3] = v.w;
            }
            float tm[16];
            #pragma unroll
            for (int k = 0; k < 16; k++) tm[k] = fmaxf(cv[k], cv[k + 16]);
            #pragma unroll
            for (int h = 8; h >= 1; h >>= 1)
                #pragma unroll
                for (int k = 0; k < h; k++) tm[k] = fmaxf(tm[k], tm[k + h]);
            const float m = tm[0];

            float S = 0.f, P = 0.f;
            #pragma unroll
            for (int k = 0; k < 8; k++) {
                float4 zv = *(const float4*)(zr + 4 * k);
                float e0 = __expf(cv[4*k]   - m);
                float e1 = __expf(cv[4*k+1] - m);
                float e2 = __expf(cv[4*k+2] - m);
                float e3 = __expf(cv[4*k+3] - m);
                S += (e0 + e1) + (e2 + e3);
                P = fmaf(e0, zv.x, P);
                P = fmaf(e1, zv.y, P);
                P = fmaf(e2, zv.z, P);
                P = fmaf(e3, zv.w, P);
            }
            const int n = s * NSLAB + lane;
            g_rec[((size_t)b * NN + n) * KREC + gw] =
                make_float2(m + __logf(S), __fdividef(P, S));
        }
        __syncthreads();                       // all warps done with buf s&1

        // ---- stage slab s+2 into buffer (s&1) ----
        if (s + 2 < SLABS) {
            #pragma unroll
            for (int kq = 0; kq < 4; kq++) {
                int i = kq * THREADS + tid;
                int limb = i >> 8, rem = i & 255, row = rem >> 3, c = rem & 7;
                const __nv_bfloat16* src = limb ? dbase1 : dbase0;
                cp16(sb + SM_D + (uint32_t)((s & 1) * 8192) + limb * 4096 +
                         row * 128 + ((c ^ (row & 7)) << 4),
                     src + (size_t)((s + 2) * NSLAB + row) * DD + c * 8);
            }
        }
        CP_COMMIT();
        CP_WAIT1();                            // slab s+1 arrived
        __syncthreads();
    }
}

// ---------------------------------------------------------------------------
// Merge: 8 threads per (b,n), 16 LSE records each, coalesced k-major reads.
// n==0 falls out naturally (all partials uniform -> pred0).
// ---------------------------------------------------------------------------
extern "C" __global__ void __launch_bounds__(256)
merge_kernel(float* __restrict__ out)
{
    const int gp = blockIdx.x * 32 + (threadIdx.x >> 3);
    const int q  = threadIdx.x & 7;
    const int b  = gp >> 8;
    const int n  = gp & 255;
    const float2* base = &g_rec[((size_t)b * NN + n) * KREC];

    float2 rec[16];
    float M = -3.4e38f;
    #pragma unroll
    for (int i = 0; i < 16; i++) {
        rec[i] = __ldg(&base[i * 8 + q]);
        M = fmaxf(M, rec[i].x);
    }
    float gM = M;
    gM = fmaxf(gM, __shfl_xor_sync(0xffffffffu, gM, 1));
    gM = fmaxf(gM, __shfl_xor_sync(0xffffffffu, gM, 2));
    gM = fmaxf(gM, __shfl_xor_sync(0xffffffffu, gM, 4));

    float S = 0.f, P = 0.f;
    #pragma unroll
    for (int i = 0; i < 16; i++) {
        float e = __expf(rec[i].x - gM);
        S += e;
        P = fmaf(rec[i].y, e, P);
    }
    S += __shfl_xor_sync(0xffffffffu, S, 1);
    P += __shfl_xor_sync(0xffffffffu, P, 1);
    S += __shfl_xor_sync(0xffffffffu, S, 2);
    P += __shfl_xor_sync(0xffffffffu, P, 2);
    S += __shfl_xor_sync(0xffffffffu, S, 4);
    P += __shfl_xor_sync(0xffffffffu, P, 4);

    if (q == 0)
        out[(size_t)b * NN + n] = P / S;
}

// ---------------------------------------------------------------------------
extern "C" void kernel_launch(void* const* d_in, const int* in_sizes, int n_in,
                              void* d_out, int out_size)
{
    const float* data    = (const float*)d_in[0];   // (64, 256, 64)
    const float* targets = (const float*)d_in[1];   // (64, 256)
    const float* W       = (const float*)d_in[2];   // (4096, 64, 1)
    float* out = (float*)d_out;                     // (64, 256)

    cudaFuncSetAttribute(main_kernel,
                         cudaFuncAttributeMaxDynamicSharedMemorySize,
                         SMEM_BYTES);

    prep_kernel<<<(DATA_ELTS + W_ELTS) / 2048, 256>>>(data, W);
    main_kernel<<<dim3(TCH, BB), THREADS, SMEM_BYTES>>>(targets);
    merge_kernel<<<512, 256>>>(out);
}

// round 12
// speedup vs baseline: 1.5170x; 1.0273x over previous
#include <cuda_runtime.h>
#include <cuda_bf16.h>
#include <math.h>
#include <stdint.h>

#define BB 64
#define NN 256
#define DD 64
#define TT 4096
#define T_TILE 128
#define TCH (TT / T_TILE)          // 32
#define THREADS 128
#define WARPS 4
#define NSLAB 32
#define SLABS (NN / NSLAB)         // 8
#define KREC 128                   // records per (b,n): 32 tc x 4 warps

#define DATA_ELTS (BB * NN * DD)   // 1048576
#define W_ELTS (TT * DD)           // 262144

// bf16 limb arrays (hi, mid), row-major d-contiguous
__device__ __align__(16) __nv_bfloat16 g_dlimb[2][DATA_ELTS];
__device__ __align__(16) __nv_bfloat16 g_wlimb[2][W_ELTS];
// per-(b, n, k) LSE records: (lse, r). 16 MB, k-contiguous for merge.
__device__ float2 g_rec[(size_t)BB * NN * KREC];

// ---- smem layout (per CTA, 84 KB -> 2 CTAs/SM) ----
#define SM_W   0                       // 2 limbs x (128 rows x 128 B)
#define SM_D   32768                   // 2 buffers x 2 limbs x (32 x 128 B)
#define SM_Z   49152                   // 32 x 132 floats
#define ZSTR   132
#define SM_CV  66048                   // 32 x 132 floats
#define SM_TGT 82944                   // 256 f32
#define SMEM_BYTES 83968

static __device__ __forceinline__ uint32_t smem_u32(const void* p) {
    uint32_t a;
    asm("{ .reg .u64 t; cvta.to.shared.u64 t, %1; cvt.u32.u64 %0, t; }"
        : "=r"(a) : "l"(p));
    return a;
}
static __device__ __forceinline__ void cp16(uint32_t dst, const void* src) {
    asm volatile("cp.async.cg.shared.global [%0], [%1], 16;" :: "r"(dst), "l"(src));
}
#define CP_COMMIT() asm volatile("cp.async.commit_group;")
#define CP_WAIT1()  asm volatile("cp.async.wait_group 1;" ::: "memory")

static __device__ __forceinline__ void ldsm4(uint32_t a, uint32_t r[4]) {
    asm volatile("ldmatrix.sync.aligned.m8n8.x4.shared.b16 {%0,%1,%2,%3}, [%4];"
                 : "=r"(r[0]), "=r"(r[1]), "=r"(r[2]), "=r"(r[3]) : "r"(a));
}
static __device__ __forceinline__ void mma16816(
    float d[4], const uint32_t a[4], uint32_t b0, uint32_t b1) {
    asm volatile(
        "mma.sync.aligned.m16n8k16.row.col.f32.bf16.bf16.f32 "
        "{%0,%1,%2,%3}, {%4,%5,%6,%7}, {%8,%9}, {%0,%1,%2,%3};"
        : "+f"(d[0]), "+f"(d[1]), "+f"(d[2]), "+f"(d[3])
        : "r"(a[0]), "r"(a[1]), "r"(a[2]), "r"(a[3]), "r"(b0), "r"(b1));
}

// ---------------------------------------------------------------------------
// Prep: fp32 -> 2 bf16 limbs (hi/mid), 8 elements per thread.
// ---------------------------------------------------------------------------
__global__ void __launch_bounds__(256)
prep_kernel(const float* __restrict__ data, const float* __restrict__ W)
{
    size_t i = ((size_t)blockIdx.x * 256 + threadIdx.x) * 8;
    const bool isW = (i >= DATA_ELTS);
    size_t j = isW ? i - DATA_ELTS : i;
    const float* src = isW ? (W + j) : (data + j);
    float4 x0 = *(const float4*)src;
    float4 x1 = *(const float4*)(src + 4);

    float v[8] = {x0.x, x0.y, x0.z, x0.w, x1.x, x1.y, x1.z, x1.w};
    uint32_t hp[4], mp[4];
    #pragma unroll
    for (int e = 0; e < 4; e++) {
        __nv_bfloat16 h0 = __float2bfloat16(v[2*e]);
        __nv_bfloat16 h1 = __float2bfloat16(v[2*e+1]);
        __nv_bfloat16 m0 = __float2bfloat16(v[2*e]   - __bfloat162float(h0));
        __nv_bfloat16 m1 = __float2bfloat16(v[2*e+1] - __bfloat162float(h1));
        __nv_bfloat162 hh = __halves2bfloat162(h0, h1);
        __nv_bfloat162 mm = __halves2bfloat162(m0, m1);
        hp[e] = *(uint32_t*)&hh;
        mp[e] = *(uint32_t*)&mm;
    }
    uint4 hv = make_uint4(hp[0], hp[1], hp[2], hp[3]);
    uint4 mv = make_uint4(mp[0], mp[1], mp[2], mp[3]);
    if (isW) {
        *(uint4*)(&g_wlimb[0][j]) = hv;
        *(uint4*)(&g_wlimb[1][j]) = mv;
    } else {
        *(uint4*)(&g_dlimb[0][j]) = hv;
        *(uint4*)(&g_dlimb[1][j]) = mv;
    }
}

// ---------------------------------------------------------------------------
// Main: 2 CTAs/SM, register-resident A+B fragments, pure-MMA inner GEMM.
// grid (TCH, BB), 128 threads.
// ---------------------------------------------------------------------------
extern "C" __global__ void __launch_bounds__(THREADS, 2)
main_kernel(const float* __restrict__ targets)
{
    extern __shared__ __align__(1024) char smem[];
    const uint32_t sb = smem_u32(smem);
    const int tc   = blockIdx.x;
    const int b    = blockIdx.y;
    const int tid  = threadIdx.x;
    const int w    = tid >> 5;
    const int lane = tid & 31;

    const __nv_bfloat16* dbase0 = &g_dlimb[0][(size_t)b * NN * DD];
    const __nv_bfloat16* dbase1 = &g_dlimb[1][(size_t)b * NN * DD];

    // ---- prologue group 0: W tile (2 limbs x 128 rows), targets, slab 0 ----
    #pragma unroll
    for (int kq = 0; kq < 16; kq++) {
        int i = kq * THREADS + tid;
        int limb = i >> 10, rem = i & 1023, row = rem >> 3, c = rem & 7;
        cp16(sb + SM_W + limb * 16384 + row * 128 + ((c ^ (row & 7)) << 4),
             &g_wlimb[limb][(size_t)(tc * T_TILE + row) * DD + c * 8]);
    }
    if (tid < 64) cp16(sb + SM_TGT + tid * 16, targets + (size_t)b * NN + tid * 4);
    {   // slab 0 -> buffer 0
        #pragma unroll
        for (int kq = 0; kq < 4; kq++) {
            int i = kq * THREADS + tid;
            int limb = i >> 8, rem = i & 255, row = rem >> 3, c = rem & 7;
            const __nv_bfloat16* src = limb ? dbase1 : dbase0;
            cp16(sb + SM_D + limb * 4096 + row * 128 + ((c ^ (row & 7)) << 4),
                 src + (size_t)row * DD + c * 8);
        }
    }
    CP_COMMIT();
    {   // group 1: slab 1 -> buffer 1
        #pragma unroll
        for (int kq = 0; kq < 4; kq++) {
            int i = kq * THREADS + tid;
            int limb = i >> 8, rem = i & 255, row = rem >> 3, c = rem & 7;
            const __nv_bfloat16* src = limb ? dbase1 : dbase0;
            cp16(sb + SM_D + 8192 + limb * 4096 + row * 128 + ((c ^ (row & 7)) << 4),
                 src + (size_t)(NSLAB + row) * DD + c * 8);
        }
    }
    CP_COMMIT();
    CP_WAIT1();                               // group 0 (W, tgt, slab0) done
    __syncthreads();

    // fragment lane decomposition
    const int l7 = lane & 7;
    const int t1 = (lane >> 3) & 1;
    const int t2 = lane >> 4;

    uint32_t xA[4], xB[4];
    #pragma unroll
    for (int k = 0; k < 4; k++) {
        xA[k] = (uint32_t)(((2 * k + t2) ^ l7) << 4);
        xB[k] = (uint32_t)(((2 * k + t1) ^ l7) << 4);
    }
    const uint32_t aRow  = sb + SM_W + (uint32_t)(32 * w + 8 * t1 + l7) * 128;
    const uint32_t bRow0 = sb + SM_D + (uint32_t)(8 * t2 + l7) * 128;

    // ---- load A fragments ONCE (invariant across slabs): 2 limbs ----
    uint32_t afrag[2][4][2][4];               // [limb][k][half][4]
    #pragma unroll
    for (int limb = 0; limb < 2; limb++)
        #pragma unroll
        for (int k = 0; k < 4; k++) {
            const uint32_t aL = aRow + (uint32_t)limb * 16384;
            ldsm4(aL + xA[k],        afrag[limb][k][0]);
            ldsm4(aL + 2048 + xA[k], afrag[limb][k][1]);
        }

    const int PA[3] = {0, 0, 1};   // (hh)(hm)(mh)
    const int PB[3] = {0, 1, 0};

    float* zw  = (float*)(smem + SM_Z);
    float* cvw = (float*)(smem + SM_CV);
    const float* s_tgt = (const float*)(smem + SM_TGT);

    float cum = 0.f;
    const int gw = tc * WARPS + w;

    const int r0 = lane >> 2;
    const int c0 = 2 * (lane & 3);

    for (int s = 0; s < SLABS; s++) {
        const uint32_t bR = bRow0 + (uint32_t)((s & 1) * 8192);

        // ---- load B fragments for this slab (2 limbs), then buffer is free
        uint32_t bfrag[2][4][2][4];
        #pragma unroll
        for (int limb = 0; limb < 2; limb++)
            #pragma unroll
            for (int k = 0; k < 4; k++) {
                const uint32_t bL = bR + (uint32_t)limb * 4096;
                ldsm4(bL + xB[k],        bfrag[limb][k][0]);
                ldsm4(bL + 2048 + xB[k], bfrag[limb][k][1]);
            }
        __syncthreads();                      // all warps done reading buf s&1

        // ---- stage slab s+2 into the freed buffer, overlaps GEMM+epilogue
        if (s + 2 < SLABS) {
            #pragma unroll
            for (int kq = 0; kq < 4; kq++) {
                int i = kq * THREADS + tid;
                int limb = i >> 8, rem = i & 255, row = rem >> 3, c = rem & 7;
                const __nv_bfloat16* src = limb ? dbase1 : dbase0;
                cp16(sb + SM_D + (uint32_t)((s & 1) * 8192) + limb * 4096 +
                         row * 128 + ((c ^ (row & 7)) << 4),
                     src + (size_t)((s + 2) * NSLAB + row) * DD + c * 8);
            }
        }
        CP_COMMIT();

        // ---- GEMM: 96 back-to-back MMAs, zero smem traffic ----
        float acc[2][4][4];
        #pragma unroll
        for (int mt = 0; mt < 2; mt++)
            #pragma unroll
            for (int q = 0; q < 4; q++)
                #pragma unroll
                for (int r = 0; r < 4; r++) acc[mt][q][r] = 0.f;

        #pragma unroll
        for (int p = 0; p < 3; p++) {
            #pragma unroll
            for (int k = 0; k < 4; k++) {
                const uint32_t* a0 = afrag[PA[p]][k][0];
                const uint32_t* a1 = afrag[PA[p]][k][1];
                const uint32_t* b0 = bfrag[PB[p]][k][0];
                const uint32_t* b1 = bfrag[PB[p]][k][1];
                mma16816(acc[0][0], a0, b0[0], b0[1]);
                mma16816(acc[0][1], a0, b0[2], b0[3]);
                mma16816(acc[0][2], a0, b1[0], b1[1]);
                mma16816(acc[0][3], a0, b1[2], b1[3]);
                mma16816(acc[1][0], a1, b0[0], b0[1]);
                mma16816(acc[1][1], a1, b0[2], b0[3]);
                mma16816(acc[1][2], a1, b1[0], b1[1]);
                mma16816(acc[1][3], a1, b1[2], b1[3]);
            }
        }

        // ---- transpose-store z[n_local][t_local] ----
        #pragma unroll
        for (int mt = 0; mt < 2; mt++) {
            const int tg = 32 * w + 16 * mt + r0;
            #pragma unroll
            for (int q = 0; q < 4; q++) {
                const int nl = 8 * q + c0;
                zw[nl * ZSTR + tg]           = acc[mt][q][0];
                zw[(nl + 1) * ZSTR + tg]     = acc[mt][q][1];
                zw[nl * ZSTR + tg + 8]       = acc[mt][q][2];
                zw[(nl + 1) * ZSTR + tg + 8] = acc[mt][q][3];
            }
        }
        __syncwarp();

        // ---- phase A: cumulative loglik scan (thread = task) ----
        #pragma unroll
        for (int j = 0; j < NSLAB; j++) {
            float z  = zw[j * ZSTR + tid];
            float tn = s_tgt[s * NSLAB + j];
            cvw[j * ZSTR + tid] = cum;
            float r = tn - z;
            cum = fmaf(-0.5f * r, r, cum);
        }
        __syncwarp();

        // ---- phase B: per-n in-lane reduction over warp's 32 tasks ----
        {
            const float* cvr = cvw + lane * ZSTR + 32 * w;
            const float* zr  = zw  + lane * ZSTR + 32 * w;

            float cv[32];
            #pragma unroll
            for (int k = 0; k < 8; k++) {
                float4 v = *(const float4*)(cvr + 4 * k);
                cv[4*k] = v.x; cv[4*k+1] = v.y; cv[4*k+2] = v.z; cv[4*k+3] = v.w;
            }
            float tm[16];
            #pragma unroll
            for (int k = 0; k < 16; k++) tm[k] = fmaxf(cv[k], cv[k + 16]);
            #pragma unroll
            for (int h = 8; h >= 1; h >>= 1)
                #pragma unroll
                for (int k = 0; k < h; k++) tm[k] = fmaxf(tm[k], tm[k + h]);
            const float m = tm[0];

            float S = 0.f, P = 0.f;
            #pragma unroll
            for (int k = 0; k < 8; k++) {
                float4 zv = *(const float4*)(zr + 4 * k);
                float e0 = __expf(cv[4*k]   - m);
                float e1 = __expf(cv[4*k+1] - m);
                float e2 = __expf(cv[4*k+2] - m);
                float e3 = __expf(cv[4*k+3] - m);
                S += (e0 + e1) + (e2 + e3);
                P = fmaf(e0, zv.x, P);
                P = fmaf(e1, zv.y, P);
                P = fmaf(e2, zv.z, P);
                P = fmaf(e3, zv.w, P);
            }
            const int n = s * NSLAB + lane;
            g_rec[((size_t)b * NN + n) * KREC + gw] =
                make_float2(m + __logf(S), __fdividef(P, S));
        }

        CP_WAIT1();                            // slab s+1 arrived
        __syncthreads();
    }
}

// ---------------------------------------------------------------------------
// Merge: 8 threads per (b,n), 16 LSE records each, coalesced k-major reads.
// n==0 falls out naturally (all partials uniform -> pred0).
// ---------------------------------------------------------------------------
extern "C" __global__ void __launch_bounds__(256)
merge_kernel(float* __restrict__ out)
{
    const int gp = blockIdx.x * 32 + (threadIdx.x >> 3);
    const int q  = threadIdx.x & 7;
    const int b  = gp >> 8;
    const int n  = gp & 255;
    const float2* base = &g_rec[((size_t)b * NN + n) * KREC];

    float2 rec[16];
    float M = -3.4e38f;
    #pragma unroll
    for (int i = 0; i < 16; i++) {
        rec[i] = __ldg(&base[i * 8 + q]);
        M = fmaxf(M, rec[i].x);
    }
    float gM = M;
    gM = fmaxf(gM, __shfl_xor_sync(0xffffffffu, gM, 1));
    gM = fmaxf(gM, __shfl_xor_sync(0xffffffffu, gM, 2));
    gM = fmaxf(gM, __shfl_xor_sync(0xffffffffu, gM, 4));

    float S = 0.f, P = 0.f;
    #pragma unroll
    for (int i = 0; i < 16; i++) {
        float e = __expf(rec[i].x - gM);
        S += e;
        P = fmaf(rec[i].y, e, P);
    }
    S += __shfl_xor_sync(0xffffffffu, S, 1);
    P += __shfl_xor_sync(0xffffffffu, P, 1);
    S += __shfl_xor_sync(0xffffffffu, S, 2);
    P += __shfl_xor_sync(0xffffffffu, P, 2);
    S += __shfl_xor_sync(0xffffffffu, S, 4);
    P += __shfl_xor_sync(0xffffffffu, P, 4);

    if (q == 0)
        out[(size_t)b * NN + n] = P / S;
}

// ---------------------------------------------------------------------------
extern "C" void kernel_launch(void* const* d_in, const int* in_sizes, int n_in,
                              void* d_out, int out_size)
{
    const float* data    = (const float*)d_in[0];   // (64, 256, 64)
    const float* targets = (const float*)d_in[1];   // (64, 256)
    const float* W       = (const float*)d_in[2];   // (4096, 64, 1)
    float* out = (float*)d_out;                     // (64, 256)

    cudaFuncSetAttribute(main_kernel,
                         cudaFuncAttributeMaxDynamicSharedMemorySize,
                         SMEM_BYTES);

    prep_kernel<<<(DATA_ELTS + W_ELTS) / 2048, 256>>>(data, W);
    main_kernel<<<dim3(TCH, BB), THREADS, SMEM_BYTES>>>(targets);
    merge_kernel<<<512, 256>>>(out);
}

// round 13
// speedup vs baseline: 1.5239x; 1.0046x over previous
#include <cuda_runtime.h>
#include <cuda_bf16.h>
#include <math.h>
#include <stdint.h>

#define BB 64
#define NN 256
#define DD 64
#define TT 4096
#define T_TILE 128
#define TCH (TT / T_TILE)          // 32
#define THREADS 128
#define WARPS 4
#define NSLAB 32
#define SLABS (NN / NSLAB)         // 8
#define KREC 128                   // records per (b,n): 32 tc x 4 warps

#define DATA_ELTS (BB * NN * DD)   // 1048576
#define W_ELTS (TT * DD)           // 262144

// bf16 limb arrays (hi, mid), row-major d-contiguous
__device__ __align__(16) __nv_bfloat16 g_dlimb[2][DATA_ELTS];
__device__ __align__(16) __nv_bfloat16 g_wlimb[2][W_ELTS];
// per-(b, n, k) LSE records: (lse, r). 16 MB, k-contiguous for merge.
__device__ float2 g_rec[(size_t)BB * NN * KREC];

// ---- smem layout (per CTA, ~98 KB -> 2 CTAs/SM) ----
// [0, 32768):   W limbs initially (limb0 @0, limb1 @16384);
//               after afrag load, reused for data slabs 0-3 (slab s @ s*8192)
// [32768,65536): data slabs 4-7 (slab s @ s*8192)
// slab slot: limb0 @ +0 (4KB), limb1 @ +4096 (4KB); rows row*128, SW8 chunks
#define SM_Z   65536                   // 32 x 132 floats
#define ZSTR   132
#define SM_CV  82432                   // 32 x 132 floats
#define SM_TGT 99328                   // 256 f32
#define SMEM_BYTES 100352

static __device__ __forceinline__ uint32_t smem_u32(const void* p) {
    uint32_t a;
    asm("{ .reg .u64 t; cvta.to.shared.u64 t, %1; cvt.u32.u64 %0, t; }"
        : "=r"(a) : "l"(p));
    return a;
}
static __device__ __forceinline__ void cp16(uint32_t dst, const void* src) {
    asm volatile("cp.async.cg.shared.global [%0], [%1], 16;" :: "r"(dst), "l"(src));
}
#define CP_COMMIT() asm volatile("cp.async.commit_group;")
#define CP_WAIT0()  asm volatile("cp.async.wait_group 0;" ::: "memory")

static __device__ __forceinline__ void ldsm4(uint32_t a, uint32_t r[4]) {
    asm volatile("ldmatrix.sync.aligned.m8n8.x4.shared.b16 {%0,%1,%2,%3}, [%4];"
                 : "=r"(r[0]), "=r"(r[1]), "=r"(r[2]), "=r"(r[3]) : "r"(a));
}
static __device__ __forceinline__ void mma16816(
    float d[4], const uint32_t a[4], uint32_t b0, uint32_t b1) {
    asm volatile(
        "mma.sync.aligned.m16n8k16.row.col.f32.bf16.bf16.f32 "
        "{%0,%1,%2,%3}, {%4,%5,%6,%7}, {%8,%9}, {%0,%1,%2,%3};"
        : "+f"(d[0]), "+f"(d[1]), "+f"(d[2]), "+f"(d[3])
        : "r"(a[0]), "r"(a[1]), "r"(a[2]), "r"(a[3]), "r"(b0), "r"(b1));
}

// ---------------------------------------------------------------------------
// Prep: fp32 -> 2 bf16 limbs (hi/mid), 8 elements per thread.
// ---------------------------------------------------------------------------
__global__ void __launch_bounds__(256)
prep_kernel(const float* __restrict__ data, const float* __restrict__ W)
{
    size_t i = ((size_t)blockIdx.x * 256 + threadIdx.x) * 8;
    const bool isW = (i >= DATA_ELTS);
    size_t j = isW ? i - DATA_ELTS : i;
    const float* src = isW ? (W + j) : (data + j);
    float4 x0 = *(const float4*)src;
    float4 x1 = *(const float4*)(src + 4);

    float v[8] = {x0.x, x0.y, x0.z, x0.w, x1.x, x1.y, x1.z, x1.w};
    uint32_t hp[4], mp[4];
    #pragma unroll
    for (int e = 0; e < 4; e++) {
        __nv_bfloat16 h0 = __float2bfloat16(v[2*e]);
        __nv_bfloat16 h1 = __float2bfloat16(v[2*e+1]);
        __nv_bfloat16 m0 = __float2bfloat16(v[2*e]   - __bfloat162float(h0));
        __nv_bfloat16 m1 = __float2bfloat16(v[2*e+1] - __bfloat162float(h1));
        __nv_bfloat162 hh = __halves2bfloat162(h0, h1);
        __nv_bfloat162 mm = __halves2bfloat162(m0, m1);
        hp[e] = *(uint32_t*)&hh;
        mp[e] = *(uint32_t*)&mm;
    }
    uint4 hv = make_uint4(hp[0], hp[1], hp[2], hp[3]);
    uint4 mv = make_uint4(mp[0], mp[1], mp[2], mp[3]);
    if (isW) {
        *(uint4*)(&g_wlimb[0][j]) = hv;
        *(uint4*)(&g_wlimb[1][j]) = mv;
    } else {
        *(uint4*)(&g_dlimb[0][j]) = hv;
        *(uint4*)(&g_dlimb[1][j]) = mv;
    }
}

// ---------------------------------------------------------------------------
// Main: 2 CTAs/SM, full data residency (W region reused), barrier-free loop.
// grid (TCH, BB), 128 threads.
// ---------------------------------------------------------------------------
extern "C" __global__ void __launch_bounds__(THREADS, 2)
main_kernel(const float* __restrict__ targets)
{
    extern __shared__ __align__(1024) char smem[];
    const uint32_t sb = smem_u32(smem);
    const int tc   = blockIdx.x;
    const int b    = blockIdx.y;
    const int tid  = threadIdx.x;
    const int w    = tid >> 5;
    const int lane = tid & 31;

    const __nv_bfloat16* dbase0 = &g_dlimb[0][(size_t)b * NN * DD];
    const __nv_bfloat16* dbase1 = &g_dlimb[1][(size_t)b * NN * DD];

    // ---- phase 1: W limbs (32 KB @0), targets, slabs 4..7 (@32768) ----
    #pragma unroll
    for (int kq = 0; kq < 16; kq++) {         // W: 2048 16B chunks
        int i = kq * THREADS + tid;
        int limb = i >> 10, rem = i & 1023, row = rem >> 3, c = rem & 7;
        cp16(sb + limb * 16384 + row * 128 + ((c ^ (row & 7)) << 4),
             &g_wlimb[limb][(size_t)(tc * T_TILE + row) * DD + c * 8]);
    }
    if (tid < 64) cp16(sb + SM_TGT + tid * 16, targets + (size_t)b * NN + tid * 4);
    #pragma unroll
    for (int kq = 0; kq < 16; kq++) {         // slabs 4..7: 2048 chunks
        int i = kq * THREADS + tid;
        int slab = 4 + (i >> 9);
        int rem  = i & 511;
        int limb = rem >> 8, r2 = rem & 255, row = r2 >> 3, c = r2 & 7;
        const __nv_bfloat16* src = limb ? dbase1 : dbase0;
        cp16(sb + slab * 8192 + limb * 4096 + row * 128 + ((c ^ (row & 7)) << 4),
             src + (size_t)(slab * NSLAB + row) * DD + c * 8);
    }
    CP_COMMIT();
    CP_WAIT0();
    __syncthreads();

    // fragment lane decomposition
    const int l7 = lane & 7;
    const int t1 = (lane >> 3) & 1;
    const int t2 = lane >> 4;

    uint32_t xA[4], xB[4];
    #pragma unroll
    for (int k = 0; k < 4; k++) {
        xA[k] = (uint32_t)(((2 * k + t2) ^ l7) << 4);
        xB[k] = (uint32_t)(((2 * k + t1) ^ l7) << 4);
    }

    // ---- load A fragments ONCE from the W region ----
    uint32_t afrag[2][4][2][4];               // [limb][k][half][4]
    {
        const uint32_t aRow = sb + (uint32_t)(32 * w + 8 * t1 + l7) * 128;
        #pragma unroll
        for (int limb = 0; limb < 2; limb++)
            #pragma unroll
            for (int k = 0; k < 4; k++) {
                const uint32_t aL = aRow + (uint32_t)limb * 16384;
                ldsm4(aL + xA[k],        afrag[limb][k][0]);
                ldsm4(aL + 2048 + xA[k], afrag[limb][k][1]);
            }
    }
    __syncthreads();                          // all warps done reading W

    // ---- phase 2: slabs 0..3 into the freed W region (@0) ----
    #pragma unroll
    for (int kq = 0; kq < 16; kq++) {
        int i = kq * THREADS + tid;
        int slab = i >> 9;
        int rem  = i & 511;
        int limb = rem >> 8, r2 = rem & 255, row = r2 >> 3, c = r2 & 7;
        const __nv_bfloat16* src = limb ? dbase1 : dbase0;
        cp16(sb + slab * 8192 + limb * 4096 + row * 128 + ((c ^ (row & 7)) << 4),
             src + (size_t)(slab * NSLAB + row) * DD + c * 8);
    }
    CP_COMMIT();
    CP_WAIT0();
    __syncthreads();                          // LAST barrier of the kernel

    const int PA[3] = {0, 0, 1};   // (hh)(hm)(mh)
    const int PB[3] = {0, 1, 0};

    float* zw  = (float*)(smem + SM_Z);
    float* cvw = (float*)(smem + SM_CV);
    const float* s_tgt = (const float*)(smem + SM_TGT);

    float cum = 0.f;
    const int gw = tc * WARPS + w;
    const uint32_t bOff = sb + (uint32_t)(8 * t2 + l7) * 128;

    const int r0 = lane >> 2;
    const int c0 = 2 * (lane & 3);

    for (int s = 0; s < SLABS; s++) {
        // ---- load B fragments for slab s (slot s*8192) ----
        uint32_t bfrag[2][4][2][4];
        const uint32_t bR = bOff + (uint32_t)(s * 8192);
        #pragma unroll
        for (int limb = 0; limb < 2; limb++)
            #pragma unroll
            for (int k = 0; k < 4; k++) {
                const uint32_t bL = bR + (uint32_t)limb * 4096;
                ldsm4(bL + xB[k],        bfrag[limb][k][0]);
                ldsm4(bL + 2048 + xB[k], bfrag[limb][k][1]);
            }

        // ---- GEMM: 96 back-to-back MMAs, zero smem traffic ----
        float acc[2][4][4];
        #pragma unroll
        for (int mt = 0; mt < 2; mt++)
            #pragma unroll
            for (int q = 0; q < 4; q++)
                #pragma unroll
                for (int r = 0; r < 4; r++) acc[mt][q][r] = 0.f;

        #pragma unroll
        for (int p = 0; p < 3; p++) {
            #pragma unroll
            for (int k = 0; k < 4; k++) {
                const uint32_t* a0 = afrag[PA[p]][k][0];
                const uint32_t* a1 = afrag[PA[p]][k][1];
                const uint32_t* b0 = bfrag[PB[p]][k][0];
                const uint32_t* b1 = bfrag[PB[p]][k][1];
                mma16816(acc[0][0], a0, b0[0], b0[1]);
                mma16816(acc[0][1], a0, b0[2], b0[3]);
                mma16816(acc[0][2], a0, b1[0], b1[1]);
                mma16816(acc[0][3], a0, b1[2], b1[3]);
                mma16816(acc[1][0], a1, b0[0], b0[1]);
                mma16816(acc[1][1], a1, b0[2], b0[3]);
                mma16816(acc[1][2], a1, b1[0], b1[1]);
                mma16816(acc[1][3], a1, b1[2], b1[3]);
            }
        }

        // ---- transpose-store z[n_local][t_local] (warp-private columns) ----
        #pragma unroll
        for (int mt = 0; mt < 2; mt++) {
            const int tg = 32 * w + 16 * mt + r0;
            #pragma unroll
            for (int q = 0; q < 4; q++) {
                const int nl = 8 * q + c0;
                zw[nl * ZSTR + tg]           = acc[mt][q][0];
                zw[(nl + 1) * ZSTR + tg]     = acc[mt][q][1];
                zw[nl * ZSTR + tg + 8]       = acc[mt][q][2];
                zw[(nl + 1) * ZSTR + tg + 8] = acc[mt][q][3];
            }
        }
        __syncwarp();

        // ---- phase A: cumulative loglik scan (thread = task) ----
        #pragma unroll
        for (int j = 0; j < NSLAB; j++) {
            float z  = zw[j * ZSTR + tid];
            float tn = s_tgt[s * NSLAB + j];
            cvw[j * ZSTR + tid] = cum;
            float r = tn - z;
            cum = fmaf(-0.5f * r, r, cum);
        }
        __syncwarp();

        // ---- phase B: per-n in-lane reduction over warp's 32 tasks ----
        {
            const float* cvr = cvw + lane * ZSTR + 32 * w;
            const float* zr  = zw  + lane * ZSTR + 32 * w;

            float cv[32];
            #pragma unroll
            for (int k = 0; k < 8; k++) {
                float4 v = *(const float4*)(cvr + 4 * k);
                cv[4*k] = v.x; cv[4*k+1] = v.y; cv[4*k+2] = v.z; cv[4*k+3] = v.w;
            }
            float tm[16];
            #pragma unroll
            for (int k = 0; k < 16; k++) tm[k] = fmaxf(cv[k], cv[k + 16]);
            #pragma unroll
            for (int h = 8; h >= 1; h >>= 1)
                #pragma unroll
                for (int k = 0; k < h; k++) tm[k] = fmaxf(tm[k], tm[k + h]);
            const float m = tm[0];

            float S = 0.f, P = 0.f;
            #pragma unroll
            for (int k = 0; k < 8; k++) {
                float4 zv = *(const float4*)(zr + 4 * k);
                float e0 = __expf(cv[4*k]   - m);
                float e1 = __expf(cv[4*k+1] - m);
                float e2 = __expf(cv[4*k+2] - m);
                float e3 = __expf(cv[4*k+3] - m);
                S += (e0 + e1) + (e2 + e3);
                P = fmaf(e0, zv.x, P);
                P = fmaf(e1, zv.y, P);
                P = fmaf(e2, zv.z, P);
                P = fmaf(e3, zv.w, P);
            }
            const int n = s * NSLAB + lane;
            g_rec[((size_t)b * NN + n) * KREC + gw] =
                make_float2(m + __logf(S), __fdividef(P, S));
        }
        __syncwarp();   // this warp's zw/cvw reads done before next slab
    }
}

// ---------------------------------------------------------------------------
// Merge: 8 threads per (b,n), 16 LSE records each, coalesced k-major reads.
// n==0 falls out naturally (all partials uniform -> pred0).
// ---------------------------------------------------------------------------
extern "C" __global__ void __launch_bounds__(256)
merge_kernel(float* __restrict__ out)
{
    const int gp = blockIdx.x * 32 + (threadIdx.x >> 3);
    const int q  = threadIdx.x & 7;
    const int b  = gp >> 8;
    const int n  = gp & 255;
    const float2* base = &g_rec[((size_t)b * NN + n) * KREC];

    float2 rec[16];
    float M = -3.4e38f;
    #pragma unroll
    for (int i = 0; i < 16; i++) {
        rec[i] = __ldg(&base[i * 8 + q]);
        M = fmaxf(M, rec[i].x);
    }
    float gM = M;
    gM = fmaxf(gM, __shfl_xor_sync(0xffffffffu, gM, 1));
    gM = fmaxf(gM, __shfl_xor_sync(0xffffffffu, gM, 2));
    gM = fmaxf(gM, __shfl_xor_sync(0xffffffffu, gM, 4));

    float S = 0.f, P = 0.f;
    #pragma unroll
    for (int i = 0; i < 16; i++) {
        float e = __expf(rec[i].x - gM);
        S += e;
        P = fmaf(rec[i].y, e, P);
    }
    S += __shfl_xor_sync(0xffffffffu, S, 1);
    P += __shfl_xor_sync(0xffffffffu, P, 1);
    S += __shfl_xor_sync(0xffffffffu, S, 2);
    P += __shfl_xor_sync(0xffffffffu, P, 2);
    S += __shfl_xor_sync(0xffffffffu, S, 4);
    P += __shfl_xor_sync(0xffffffffu, P, 4);

    if (q == 0)
        out[(size_t)b * NN + n] = P / S;
}

// ---------------------------------------------------------------------------
extern "C" void kernel_launch(void* const* d_in, const int* in_sizes, int n_in,
                              void* d_out, int out_size)
{
    const float* data    = (const float*)d_in[0];   // (64, 256, 64)
    const float* targets = (const float*)d_in[1];   // (64, 256)
    const float* W       = (const float*)d_in[2];   // (4096, 64, 1)
    float* out = (float*)d_out;                     // (64, 256)

    cudaFuncSetAttribute(main_kernel,
                         cudaFuncAttributeMaxDynamicSharedMemorySize,
                         SMEM_BYTES);

    prep_kernel<<<(DATA_ELTS + W_ELTS) / 2048, 256>>>(data, W);
    main_kernel<<<dim3(TCH, BB), THREADS, SMEM_BYTES>>>(targets);
    merge_kernel<<<512, 256>>>(out);
}

// round 14
// speedup vs baseline: 1.5384x; 1.0095x over previous
#include <cuda_runtime.h>
#include <cuda_fp16.h>
#include <math.h>
#include <stdint.h>

#define BB 64
#define NN 256
#define DD 64
#define TT 4096
#define T_TILE 128
#define TCH (TT / T_TILE)          // 32
#define THREADS 128
#define WARPS 4
#define NSLAB 32
#define SLABS (NN / NSLAB)         // 8
#define KREC 128                   // records per (b,n): 32 tc x 4 warps

#define DATA_ELTS (BB * NN * DD)   // 1048576
#define W_ELTS (TT * DD)           // 262144

// fp16 limb arrays (hi, mid), row-major d-contiguous
__device__ __align__(16) __half g_dlimb[2][DATA_ELTS];
__device__ __align__(16) __half g_wlimb[2][W_ELTS];
// per-(b, n, k) LSE records: (lse, r). 16 MB, k-contiguous for merge.
__device__ float2 g_rec[(size_t)BB * NN * KREC];

// ---- smem layout (per CTA, ~98 KB -> 2 CTAs/SM) ----
// [0, 32768):   W limbs initially; after afrag load, data slabs 0-3
// [32768,65536): data slabs 4-7 (slab s @ s*8192; limb0 +0, limb1 +4096)
#define SM_Z   65536                   // 32 x 132 floats
#define ZSTR   132
#define SM_CV  82432                   // 32 x 132 floats
#define SM_TGT 99328                   // 256 f32
#define SMEM_BYTES 100352

static __device__ __forceinline__ uint32_t smem_u32(const void* p) {
    uint32_t a;
    asm("{ .reg .u64 t; cvta.to.shared.u64 t, %1; cvt.u32.u64 %0, t; }"
        : "=r"(a) : "l"(p));
    return a;
}
static __device__ __forceinline__ void cp16(uint32_t dst, const void* src) {
    asm volatile("cp.async.cg.shared.global [%0], [%1], 16;" :: "r"(dst), "l"(src));
}
#define CP_COMMIT() asm volatile("cp.async.commit_group;")
#define CP_WAIT0()  asm volatile("cp.async.wait_group 0;" ::: "memory")

static __device__ __forceinline__ void ldsm4(uint32_t a, uint32_t r[4]) {
    asm volatile("ldmatrix.sync.aligned.m8n8.x4.shared.b16 {%0,%1,%2,%3}, [%4];"
                 : "=r"(r[0]), "=r"(r[1]), "=r"(r[2]), "=r"(r[3]) : "r"(a));
}
// f32-accumulate fp16 MMA (main product)
static __device__ __forceinline__ void mma_f32(
    float d[4], const uint32_t a[4], uint32_t b0, uint32_t b1) {
    asm volatile(
        "mma.sync.aligned.m16n8k16.row.col.f32.f16.f16.f32 "
        "{%0,%1,%2,%3}, {%4,%5,%6,%7}, {%8,%9}, {%0,%1,%2,%3};"
        : "+f"(d[0]), "+f"(d[1]), "+f"(d[2]), "+f"(d[3])
        : "r"(a[0]), "r"(a[1]), "r"(a[2]), "r"(a[3]), "r"(b0), "r"(b1));
}
// f16-accumulate fp16 MMA (correction products) — 2-reg accumulator
static __device__ __forceinline__ void mma_f16(
    uint32_t d[2], const uint32_t a[4], uint32_t b0, uint32_t b1) {
    asm volatile(
        "mma.sync.aligned.m16n8k16.row.col.f16.f16.f16.f16 "
        "{%0,%1}, {%2,%3,%4,%5}, {%6,%7}, {%0,%1};"
        : "+r"(d[0]), "+r"(d[1])
        : "r"(a[0]), "r"(a[1]), "r"(a[2]), "r"(a[3]), "r"(b0), "r"(b1));
}

// ---------------------------------------------------------------------------
// Prep: fp32 -> 2 fp16 limbs (hi/mid), 8 elements per thread.
// ---------------------------------------------------------------------------
__global__ void __launch_bounds__(256)
prep_kernel(const float* __restrict__ data, const float* __restrict__ W)
{
    size_t i = ((size_t)blockIdx.x * 256 + threadIdx.x) * 8;
    const bool isW = (i >= DATA_ELTS);
    size_t j = isW ? i - DATA_ELTS : i;
    const float* src = isW ? (W + j) : (data + j);
    float4 x0 = *(const float4*)src;
    float4 x1 = *(const float4*)(src + 4);

    float v[8] = {x0.x, x0.y, x0.z, x0.w, x1.x, x1.y, x1.z, x1.w};
    uint32_t hp[4], mp[4];
    #pragma unroll
    for (int e = 0; e < 4; e++) {
        __half h0 = __float2half_rn(v[2*e]);
        __half h1 = __float2half_rn(v[2*e+1]);
        __half m0 = __float2half_rn(v[2*e]   - __half2float(h0));
        __half m1 = __float2half_rn(v[2*e+1] - __half2float(h1));
        __half2 hh = __halves2half2(h0, h1);
        __half2 mm = __halves2half2(m0, m1);
        hp[e] = *(uint32_t*)&hh;
        mp[e] = *(uint32_t*)&mm;
    }
    uint4 hv = make_uint4(hp[0], hp[1], hp[2], hp[3]);
    uint4 mv = make_uint4(mp[0], mp[1], mp[2], mp[3]);
    if (isW) {
        *(uint4*)(&g_wlimb[0][j]) = hv;
        *(uint4*)(&g_wlimb[1][j]) = mv;
    } else {
        *(uint4*)(&g_dlimb[0][j]) = hv;
        *(uint4*)(&g_dlimb[1][j]) = mv;
    }
}

// ---------------------------------------------------------------------------
// Main: 2 CTAs/SM, full data residency, barrier-free loop,
// hh in f32-accum + (hm, mh) in f16-accum MMAs.
// grid (TCH, BB), 128 threads.
// ---------------------------------------------------------------------------
extern "C" __global__ void __launch_bounds__(THREADS, 2)
main_kernel(const float* __restrict__ targets)
{
    extern __shared__ __align__(1024) char smem[];
    const uint32_t sb = smem_u32(smem);
    const int tc   = blockIdx.x;
    const int b    = blockIdx.y;
    const int tid  = threadIdx.x;
    const int w    = tid >> 5;
    const int lane = tid & 31;

    const __half* dbase0 = &g_dlimb[0][(size_t)b * NN * DD];
    const __half* dbase1 = &g_dlimb[1][(size_t)b * NN * DD];

    // ---- phase 1: W limbs (32 KB @0), targets, slabs 4..7 (@32768) ----
    #pragma unroll
    for (int kq = 0; kq < 16; kq++) {
        int i = kq * THREADS + tid;
        int limb = i >> 10, rem = i & 1023, row = rem >> 3, c = rem & 7;
        cp16(sb + limb * 16384 + row * 128 + ((c ^ (row & 7)) << 4),
             &g_wlimb[limb][(size_t)(tc * T_TILE + row) * DD + c * 8]);
    }
    if (tid < 64) cp16(sb + SM_TGT + tid * 16, targets + (size_t)b * NN + tid * 4);
    #pragma unroll
    for (int kq = 0; kq < 16; kq++) {
        int i = kq * THREADS + tid;
        int slab = 4 + (i >> 9);
        int rem  = i & 511;
        int limb = rem >> 8, r2 = rem & 255, row = r2 >> 3, c = r2 & 7;
        const __half* src = limb ? dbase1 : dbase0;
        cp16(sb + slab * 8192 + limb * 4096 + row * 128 + ((c ^ (row & 7)) << 4),
             src + (size_t)(slab * NSLAB + row) * DD + c * 8);
    }
    CP_COMMIT();
    CP_WAIT0();
    __syncthreads();

    // fragment lane decomposition
    const int l7 = lane & 7;
    const int t1 = (lane >> 3) & 1;
    const int t2 = lane >> 4;

    uint32_t xA[4], xB[4];
    #pragma unroll
    for (int k = 0; k < 4; k++) {
        xA[k] = (uint32_t)(((2 * k + t2) ^ l7) << 4);
        xB[k] = (uint32_t)(((2 * k + t1) ^ l7) << 4);
    }

    // ---- load A fragments ONCE from the W region ----
    uint32_t afrag[2][4][2][4];               // [limb][k][half][4]
    {
        const uint32_t aRow = sb + (uint32_t)(32 * w + 8 * t1 + l7) * 128;
        #pragma unroll
        for (int limb = 0; limb < 2; limb++)
            #pragma unroll
            for (int k = 0; k < 4; k++) {
                const uint32_t aL = aRow + (uint32_t)limb * 16384;
                ldsm4(aL + xA[k],        afrag[limb][k][0]);
                ldsm4(aL + 2048 + xA[k], afrag[limb][k][1]);
            }
    }
    __syncthreads();                          // all warps done reading W

    // ---- phase 2: slabs 0..3 into the freed W region (@0) ----
    #pragma unroll
    for (int kq = 0; kq < 16; kq++) {
        int i = kq * THREADS + tid;
        int slab = i >> 9;
        int rem  = i & 511;
        int limb = rem >> 8, r2 = rem & 255, row = r2 >> 3, c = r2 & 7;
        const __half* src = limb ? dbase1 : dbase0;
        cp16(sb + slab * 8192 + limb * 4096 + row * 128 + ((c ^ (row & 7)) << 4),
             src + (size_t)(slab * NSLAB + row) * DD + c * 8);
    }
    CP_COMMIT();
    CP_WAIT0();
    __syncthreads();                          // LAST barrier of the kernel

    float* zw  = (float*)(smem + SM_Z);
    float* cvw = (float*)(smem + SM_CV);
    const float* s_tgt = (const float*)(smem + SM_TGT);

    float cum = 0.f;
    const int gw = tc * WARPS + w;
    const uint32_t bOff = sb + (uint32_t)(8 * t2 + l7) * 128;

    const int r0 = lane >> 2;
    const int c0 = 2 * (lane & 3);

    for (int s = 0; s < SLABS; s++) {
        // ---- load B fragments for slab s ----
        uint32_t bfrag[2][4][2][4];
        const uint32_t bR = bOff + (uint32_t)(s * 8192);
        #pragma unroll
        for (int limb = 0; limb < 2; limb++)
            #pragma unroll
            for (int k = 0; k < 4; k++) {
                const uint32_t bL = bR + (uint32_t)limb * 4096;
                ldsm4(bL + xB[k],        bfrag[limb][k][0]);
                ldsm4(bL + 2048 + xB[k], bfrag[limb][k][1]);
            }

        // ---- GEMM: hh (f32 acc) + hm + mh (f16 acc) ----
        float acc[2][4][4];
        uint32_t accc[2][4][2];
        #pragma unroll
        for (int mt = 0; mt < 2; mt++)
            #pragma unroll
            for (int q = 0; q < 4; q++) {
                acc[mt][q][0] = acc[mt][q][1] = 0.f;
                acc[mt][q][2] = acc[mt][q][3] = 0.f;
                accc[mt][q][0] = 0u; accc[mt][q][1] = 0u;
            }

        #pragma unroll
        for (int k = 0; k < 4; k++) {
            const uint32_t* ah0 = afrag[0][k][0];
            const uint32_t* ah1 = afrag[0][k][1];
            const uint32_t* am0 = afrag[1][k][0];
            const uint32_t* am1 = afrag[1][k][1];
            const uint32_t* bh0 = bfrag[0][k][0];
            const uint32_t* bh1 = bfrag[0][k][1];
            const uint32_t* bm0 = bfrag[1][k][0];
            const uint32_t* bm1 = bfrag[1][k][1];

            // main: h*h, f32 accum
            mma_f32(acc[0][0], ah0, bh0[0], bh0[1]);
            mma_f32(acc[0][1], ah0, bh0[2], bh0[3]);
            mma_f32(acc[0][2], ah0, bh1[0], bh1[1]);
            mma_f32(acc[0][3], ah0, bh1[2], bh1[3]);
            mma_f32(acc[1][0], ah1, bh0[0], bh0[1]);
            mma_f32(acc[1][1], ah1, bh0[2], bh0[3]);
            mma_f32(acc[1][2], ah1, bh1[0], bh1[1]);
            mma_f32(acc[1][3], ah1, bh1[2], bh1[3]);

            // corrections: h*m and m*h, f16 accum
            mma_f16(accc[0][0], ah0, bm0[0], bm0[1]);
            mma_f16(accc[0][1], ah0, bm0[2], bm0[3]);
            mma_f16(accc[0][2], ah0, bm1[0], bm1[1]);
            mma_f16(accc[0][3], ah0, bm1[2], bm1[3]);
            mma_f16(accc[1][0], ah1, bm0[0], bm0[1]);
            mma_f16(accc[1][1], ah1, bm0[2], bm0[3]);
            mma_f16(accc[1][2], ah1, bm1[0], bm1[1]);
            mma_f16(accc[1][3], ah1, bm1[2], bm1[3]);

            mma_f16(accc[0][0], am0, bh0[0], bh0[1]);
            mma_f16(accc[0][1], am0, bh0[2], bh0[3]);
            mma_f16(accc[0][2], am0, bh1[0], bh1[1]);
            mma_f16(accc[0][3], am0, bh1[2], bh1[3]);
            mma_f16(accc[1][0], am1, bh0[0], bh0[1]);
            mma_f16(accc[1][1], am1, bh0[2], bh0[3]);
            mma_f16(accc[1][2], am1, bh1[0], bh1[1]);
            mma_f16(accc[1][3], am1, bh1[2], bh1[3]);
        }

        // ---- combine f16 corrections into f32 accumulators ----
        #pragma unroll
        for (int mt = 0; mt < 2; mt++)
            #pragma unroll
            for (int q = 0; q < 4; q++) {
                __half2 p0 = *reinterpret_cast<__half2*>(&accc[mt][q][0]);
                __half2 p1 = *reinterpret_cast<__half2*>(&accc[mt][q][1]);
                acc[mt][q][0] += __low2float(p0);
                acc[mt][q][1] += __high2float(p0);
                acc[mt][q][2] += __low2float(p1);
                acc[mt][q][3] += __high2float(p1);
            }

        // ---- transpose-store z[n_local][t_local] (warp-private columns) ----
        #pragma unroll
        for (int mt = 0; mt < 2; mt++) {
            const int tg = 32 * w + 16 * mt + r0;
            #pragma unroll
            for (int q = 0; q < 4; q++) {
                const int nl = 8 * q + c0;
                zw[nl * ZSTR + tg]           = acc[mt][q][0];
                zw[(nl + 1) * ZSTR + tg]     = acc[mt][q][1];
                zw[nl * ZSTR + tg + 8]       = acc[mt][q][2];
                zw[(nl + 1) * ZSTR + tg + 8] = acc[mt][q][3];
            }
        }
        __syncwarp();

        // ---- phase A: cumulative loglik scan (thread = task) ----
        #pragma unroll
        for (int j = 0; j < NSLAB; j++) {
            float z  = zw[j * ZSTR + tid];
            float tn = s_tgt[s * NSLAB + j];
            cvw[j * ZSTR + tid] = cum;
            float r = tn - z;
            cum = fmaf(-0.5f * r, r, cum);
        }
        __syncwarp();

        // ---- phase B: per-n in-lane reduction over warp's 32 tasks ----
        {
            const float* cvr = cvw + lane * ZSTR + 32 * w;
            const float* zr  = zw  + lane * ZSTR + 32 * w;

            float cv[32];
            #pragma unroll
            for (int k = 0; k < 8; k++) {
                float4 v = *(const float4*)(cvr + 4 * k);
                cv[4*k] = v.x; cv[4*k+1] = v.y; cv[4*k+2] = v.z; cv[4*k+3] = v.w;
            }
            float tm[16];
            #pragma unroll
            for (int k = 0; k < 16; k++) tm[k] = fmaxf(cv[k], cv[k + 16]);
            #pragma unroll
            for (int h = 8; h >= 1; h >>= 1)
                #pragma unroll
                for (int k = 0; k < h; k++) tm[k] = fmaxf(tm[k], tm[k + h]);
            const float m = tm[0];

            float S = 0.f, P = 0.f;
            #pragma unroll
            for (int k = 0; k < 8; k++) {
                float4 zv = *(const float4*)(zr + 4 * k);
                float e0 = __expf(cv[4*k]   - m);
                float e1 = __expf(cv[4*k+1] - m);
                float e2 = __expf(cv[4*k+2] - m);
                float e3 = __expf(cv[4*k+3] - m);
                S += (e0 + e1) + (e2 + e3);
                P = fmaf(e0, zv.x, P);
                P = fmaf(e1, zv.y, P);
                P = fmaf(e2, zv.z, P);
                P = fmaf(e3, zv.w, P);
            }
            const int n = s * NSLAB + lane;
            g_rec[((size_t)b * NN + n) * KREC + gw] =
                make_float2(m + __logf(S), __fdividef(P, S));
        }
        __syncwarp();   // this warp's zw/cvw reads done before next slab
    }
}

// ---------------------------------------------------------------------------
// Merge: 8 threads per (b,n), 16 LSE records each, coalesced k-major reads.
// n==0 falls out naturally (all partials uniform -> pred0).
// ---------------------------------------------------------------------------
extern "C" __global__ void __launch_bounds__(256)
merge_kernel(float* __restrict__ out)
{
    const int gp = blockIdx.x * 32 + (threadIdx.x >> 3);
    const int q  = threadIdx.x & 7;
    const int b  = gp >> 8;
    const int n  = gp & 255;
    const float2* base = &g_rec[((size_t)b * NN + n) * KREC];

    float2 rec[16];
    float M = -3.4e38f;
    #pragma unroll
    for (int i = 0; i < 16; i++) {
        rec[i] = __ldg(&base[i * 8 + q]);
        M = fmaxf(M, rec[i].x);
    }
    float gM = M;
    gM = fmaxf(gM, __shfl_xor_sync(0xffffffffu, gM, 1));
    gM = fmaxf(gM, __shfl_xor_sync(0xffffffffu, gM, 2));
    gM = fmaxf(gM, __shfl_xor_sync(0xffffffffu, gM, 4));

    float S = 0.f, P = 0.f;
    #pragma unroll
    for (int i = 0; i < 16; i++) {
        float e = __expf(rec[i].x - gM);
        S += e;
        P = fmaf(rec[i].y, e, P);
    }
    S += __shfl_xor_sync(0xffffffffu, S, 1);
    P += __shfl_xor_sync(0xffffffffu, P, 1);
    S += __shfl_xor_sync(0xffffffffu, S, 2);
    P += __shfl_xor_sync(0xffffffffu, P, 2);
    S += __shfl_xor_sync(0xffffffffu, S, 4);
    P += __shfl_xor_sync(0xffffffffu, P, 4);

    if (q == 0)
        out[(size_t)b * NN + n] = P / S;
}

// ---------------------------------------------------------------------------
extern "C" void kernel_launch(void* const* d_in, const int* in_sizes, int n_in,
                              void* d_out, int out_size)
{
    const float* data    = (const float*)d_in[0];   // (64, 256, 64)
    const float* targets = (const float*)d_in[1];   // (64, 256)
    const float* W       = (const float*)d_in[2];   // (4096, 64, 1)
    float* out = (float*)d_out;                     // (64, 256)

    cudaFuncSetAttribute(main_kernel,
                         cudaFuncAttributeMaxDynamicSharedMemorySize,
                         SMEM_BYTES);

    prep_kernel<<<(DATA_ELTS + W_ELTS) / 2048, 256>>>(data, W);
    main_kernel<<<dim3(TCH, BB), THREADS, SMEM_BYTES>>>(targets);
    merge_kernel<<<512, 256>>>(out);
}